// round 17
// baseline (speedup 1.0000x reference)
#include <cuda_runtime.h>
#include <cstdint>

// y = (U kron I2) @ x, U[i,i+1] = sqrt(i+1)
// x: (2D, B) fp32, D=4096, B=4096.
// out[r] = sqrt(r/2 + 1) * x[r+2] (rowwise), last two rows zero.
//
// FINAL (session-best, R16-measured): bench 43.488us, ncu 36.06us,
// DRAM 74.5% = 5.90 TB/s — the GB300 mixed rd+wr HBM stream ceiling.
// Traffic (128 MiB read + 128 MiB write) is irreducible; SM side idle
// (issue 5.4%, alu 1.2%). All levers tested R1-R16; none moves DRAM%.
//
// Row-pair geometry: one block per row pair (rows 2i, 2i+1 share
// coef = sqrt(i+1)), 256 threads x 4 x 32B sweeps = 32 KiB/block.
// Blackwell 256-bit streaming accesses (ld/st.global.cs.v8.f32) halve
// LDG/STG count per byte vs float4 — best measured ncu dur + DRAM%.

static constexpr int D = 4096;
static constexpr int B_ELEMS = 4096;               // floats per row
static constexpr int PAIR_ELEMS = 2 * B_ELEMS;     // 8192 floats per row pair
static constexpr int NPAIRS = D;                   // 4096 blocks
static constexpr int LAST_PAIR = D - 1;            // pair i = D-1 is all zero

__device__ __forceinline__ void ld_v8_cs(const float* p, float* v) {
    asm volatile("ld.global.cs.v8.f32 {%0,%1,%2,%3,%4,%5,%6,%7}, [%8];"
                 : "=f"(v[0]), "=f"(v[1]), "=f"(v[2]), "=f"(v[3]),
                   "=f"(v[4]), "=f"(v[5]), "=f"(v[6]), "=f"(v[7])
                 : "l"(p));
}

__device__ __forceinline__ void st_v8_cs(float* p, const float* v) {
    asm volatile("st.global.cs.v8.f32 [%0], {%1,%2,%3,%4,%5,%6,%7,%8};"
                 :: "l"(p),
                    "f"(v[0]), "f"(v[1]), "f"(v[2]), "f"(v[3]),
                    "f"(v[4]), "f"(v[5]), "f"(v[6]), "f"(v[7])
                 : "memory");
}

__global__ void __launch_bounds__(256) destroy_kernel(const float* __restrict__ in,
                                                      float* __restrict__ out) {
    const int pair = blockIdx.x;
    const int tid = threadIdx.x;
    float* opair = out + (size_t)pair * PAIR_ELEMS;

    if (pair < LAST_PAIR) {
        const float coef = sqrtf((float)(pair + 1));
        const float* ipair = in + (size_t)(pair + 1) * PAIR_ELEMS;  // shift by 2 rows

        // 4 sweeps: 256 threads x 8 floats = 2048 floats per sweep.
        float v[4][8];
#pragma unroll
        for (int k = 0; k < 4; k++)
            ld_v8_cs(ipair + tid * 8 + k * 2048, v[k]);

#pragma unroll
        for (int k = 0; k < 4; k++)
#pragma unroll
            for (int j = 0; j < 8; j++)
                v[k][j] *= coef;

#pragma unroll
        for (int k = 0; k < 4; k++)
            st_v8_cs(opair + tid * 8 + k * 2048, v[k]);
    } else {
        float z[8] = {0.f, 0.f, 0.f, 0.f, 0.f, 0.f, 0.f, 0.f};
#pragma unroll
        for (int k = 0; k < 4; k++)
            st_v8_cs(opair + tid * 8 + k * 2048, z);
    }
}

extern "C" void kernel_launch(void* const* d_in, const int* in_sizes, int n_in,
                              void* d_out, int out_size) {
    const float* in = (const float*)d_in[0];
    float* out = (float*)d_out;
    destroy_kernel<<<NPAIRS, 256>>>(in, out);
}